// round 1
// baseline (speedup 1.0000x reference)
#include <cuda_runtime.h>
#include <math.h>

// Problem constants (fixed shapes from the reference)
#define N_BATCH 64
#define DIM     512   // d (contraction for QK)
#define CQ      512   // c (query positions)
#define TT      1024  // t = h*w
#define WW      128   // w
#define SCALE   0.04419417382415922f  // 512^-0.5

// 128 MB scratch for logits/weights [n][c][t] (device global: allowed, no cudaMalloc)
static __device__ float g_logits[(size_t)N_BATCH * CQ * TT];

#define BM 128
#define BN 128
#define BK 8

// ---------------------------------------------------------------------------
// GEMM1 (TN): L[n][c][t] = SCALE * sum_d Q[n][d][c] * K[n][d][t]
// Contraction dim d is the slow (row) dim for BOTH operands -> coalesced
// float4 tile loads straight into As[k][m], Bs[k][n]. 128x128x8 tiling,
// 256 threads, 8x8 register micro-tile.
// ---------------------------------------------------------------------------
__global__ __launch_bounds__(256) void gemm_qk_kernel(
    const float* __restrict__ Q, const float* __restrict__ Kp,
    float* __restrict__ L)
{
    const int n  = blockIdx.z;
    const float* Qb = Q  + (size_t)n * DIM * CQ;
    const float* Kb = Kp + (size_t)n * DIM * TT;
    float*       Lb = L  + (size_t)n * CQ  * TT;
    const int c0 = blockIdx.y * BM;
    const int t0 = blockIdx.x * BN;

    __shared__ float As[BK][BM];
    __shared__ float Bs[BK][BN];

    const int tid  = threadIdx.x;
    const int arow = tid >> 5;         // 0..7   (k within tile)
    const int acol = (tid & 31) << 2;  // 0..124 (float4 column)

    const int ty = tid >> 4;           // 0..15
    const int tx = tid & 15;           // 0..15
    const int mBase = ty * 8;
    const int nBase = tx * 8;

    float acc[8][8];
    #pragma unroll
    for (int i = 0; i < 8; i++)
        #pragma unroll
        for (int j = 0; j < 8; j++) acc[i][j] = 0.f;

    for (int k0 = 0; k0 < DIM; k0 += BK) {
        float4 a4 = *(const float4*)(Qb + (size_t)(k0 + arow) * CQ + c0 + acol);
        float4 b4 = *(const float4*)(Kb + (size_t)(k0 + arow) * TT + t0 + acol);
        *(float4*)(&As[arow][acol]) = a4;
        *(float4*)(&Bs[arow][acol]) = b4;
        __syncthreads();

        #pragma unroll
        for (int k = 0; k < BK; k++) {
            float a[8], b[8];
            *(float4*)(a + 0) = *(const float4*)(&As[k][mBase + 0]);
            *(float4*)(a + 4) = *(const float4*)(&As[k][mBase + 4]);
            *(float4*)(b + 0) = *(const float4*)(&Bs[k][nBase + 0]);
            *(float4*)(b + 4) = *(const float4*)(&Bs[k][nBase + 4]);
            #pragma unroll
            for (int i = 0; i < 8; i++)
                #pragma unroll
                for (int j = 0; j < 8; j++)
                    acc[i][j] = fmaf(a[i], b[j], acc[i][j]);
        }
        __syncthreads();
    }

    #pragma unroll
    for (int i = 0; i < 8; i++) {
        float* out = Lb + (size_t)(c0 + mBase + i) * TT + t0 + nBase;
        #pragma unroll
        for (int j = 0; j < 8; j += 4) {
            float4 o = make_float4(acc[i][j+0] * SCALE, acc[i][j+1] * SCALE,
                                   acc[i][j+2] * SCALE, acc[i][j+3] * SCALE);
            *(float4*)(out + j) = o;
        }
    }
}

// ---------------------------------------------------------------------------
// Fused mask + softmax over t for each (n, c) row. Mask: (t % 128) < vw[n],
// vw = min(128, floor(128*ratio + 0.5)) — matches the JAX fp32 formula.
// 256 threads, 1 float4 each.
// ---------------------------------------------------------------------------
__global__ __launch_bounds__(256) void softmax_mask_kernel(
    float* __restrict__ L, const float* __restrict__ ratios)
{
    const int row = blockIdx.x;        // 0 .. N_BATCH*CQ-1
    const int n   = row >> 9;          // / CQ
    float* p = L + (size_t)row * TT;

    const float ratio = ratios[n];
    int vw = (int)floorf((float)WW * ratio + 0.5f);
    vw = vw > WW ? WW : vw;

    const int tid  = threadIdx.x;
    const int base = tid << 2;
    float4 v = ((const float4*)p)[tid];
    float vals[4] = {v.x, v.y, v.z, v.w};
    #pragma unroll
    for (int i = 0; i < 4; i++) {
        int wi = (base + i) & (WW - 1);
        if (wi >= vw) vals[i] = -INFINITY;
    }

    __shared__ float red_max[8];
    __shared__ float red_sum[8];
    const int lane = tid & 31;
    const int warp = tid >> 5;

    // --- max reduce ---
    float m = fmaxf(fmaxf(vals[0], vals[1]), fmaxf(vals[2], vals[3]));
    #pragma unroll
    for (int off = 16; off > 0; off >>= 1)
        m = fmaxf(m, __shfl_xor_sync(0xffffffffu, m, off));
    if (lane == 0) red_max[warp] = m;
    __syncthreads();
    float mall = red_max[0];
    #pragma unroll
    for (int i = 1; i < 8; i++) mall = fmaxf(mall, red_max[i]);

    // --- exp + sum reduce ---
    float s = 0.f;
    #pragma unroll
    for (int i = 0; i < 4; i++) {
        vals[i] = expf(vals[i] - mall);   // expf(-inf - m) = 0 for masked
        s += vals[i];
    }
    #pragma unroll
    for (int off = 16; off > 0; off >>= 1)
        s += __shfl_xor_sync(0xffffffffu, s, off);
    if (lane == 0) red_sum[warp] = s;
    __syncthreads();
    float sall = 0.f;
    #pragma unroll
    for (int i = 0; i < 8; i++) sall += red_sum[i];

    const float inv = 1.0f / sall;
    float4 o = make_float4(vals[0] * inv, vals[1] * inv, vals[2] * inv, vals[3] * inv);
    ((float4*)p)[tid] = o;
}

// ---------------------------------------------------------------------------
// GEMM2 (NT): O[n][d][c] = sum_t V[n][d][t] * W[n][c][t]
// Contraction dim t is contiguous for both -> float4 loads along t, transposed
// smem stores (padded rows avoid conflicts). 128x128x8, 8x8 micro-tile.
// ---------------------------------------------------------------------------
__global__ __launch_bounds__(256) void gemm_wv_kernel(
    const float* __restrict__ V, const float* __restrict__ W,
    float* __restrict__ O)
{
    const int n  = blockIdx.z;
    const float* Vb = V + (size_t)n * DIM * TT;
    const float* Wb = W + (size_t)n * CQ  * TT;
    float*       Ob = O + (size_t)n * DIM * CQ;
    const int d0 = blockIdx.y * BM;
    const int c0 = blockIdx.x * BN;

    __shared__ float As[BK][BM + 4];
    __shared__ float Bs[BK][BN + 4];

    const int tid  = threadIdx.x;
    const int lrow = tid >> 1;          // 0..127
    const int lseg = (tid & 1) << 2;    // 0 or 4

    const int ty = tid >> 4;
    const int tx = tid & 15;
    const int mBase = ty * 8;
    const int nBase = tx * 8;

    float acc[8][8];
    #pragma unroll
    for (int i = 0; i < 8; i++)
        #pragma unroll
        for (int j = 0; j < 8; j++) acc[i][j] = 0.f;

    for (int k0 = 0; k0 < TT; k0 += BK) {
        float4 a4 = *(const float4*)(Vb + (size_t)(d0 + lrow) * TT + k0 + lseg);
        float4 b4 = *(const float4*)(Wb + (size_t)(c0 + lrow) * TT + k0 + lseg);
        As[lseg + 0][lrow] = a4.x;
        As[lseg + 1][lrow] = a4.y;
        As[lseg + 2][lrow] = a4.z;
        As[lseg + 3][lrow] = a4.w;
        Bs[lseg + 0][lrow] = b4.x;
        Bs[lseg + 1][lrow] = b4.y;
        Bs[lseg + 2][lrow] = b4.z;
        Bs[lseg + 3][lrow] = b4.w;
        __syncthreads();

        #pragma unroll
        for (int k = 0; k < BK; k++) {
            float a[8], b[8];
            #pragma unroll
            for (int i = 0; i < 8; i++) a[i] = As[k][mBase + i];
            #pragma unroll
            for (int j = 0; j < 8; j++) b[j] = Bs[k][nBase + j];
            #pragma unroll
            for (int i = 0; i < 8; i++)
                #pragma unroll
                for (int j = 0; j < 8; j++)
                    acc[i][j] = fmaf(a[i], b[j], acc[i][j]);
        }
        __syncthreads();
    }

    #pragma unroll
    for (int i = 0; i < 8; i++) {
        float* out = Ob + (size_t)(d0 + mBase + i) * CQ + c0 + nBase;
        #pragma unroll
        for (int j = 0; j < 8; j += 4) {
            float4 o = make_float4(acc[i][j+0], acc[i][j+1], acc[i][j+2], acc[i][j+3]);
            *(float4*)(out + j) = o;
        }
    }
}

// ---------------------------------------------------------------------------
extern "C" void kernel_launch(void* const* d_in, const int* in_sizes, int n_in,
                              void* d_out, int out_size)
{
    const float* query  = (const float*)d_in[0];  // [64, 512, 512]
    const float* key    = (const float*)d_in[1];  // [64, 512, 1024]
    const float* value  = (const float*)d_in[2];  // [64, 512, 1024]
    const float* ratios = (const float*)d_in[3];  // [64]
    float* out = (float*)d_out;                   // [64, 512, 512]

    float* logits = nullptr;
    cudaGetSymbolAddress((void**)&logits, g_logits);

    // 1) logits = Q^T K * SCALE
    {
        dim3 grid(TT / BN, CQ / BM, N_BATCH);  // (8, 4, 64)
        gemm_qk_kernel<<<grid, 256>>>(query, key, logits);
    }
    // 2) mask + softmax (in place)
    {
        softmax_mask_kernel<<<N_BATCH * CQ, 256>>>(logits, ratios);
    }
    // 3) out = weights @ V^T  (per batch, NT)
    {
        dim3 grid(CQ / BN, DIM / BM, N_BATCH);  // (4, 4, 64)
        gemm_wv_kernel<<<grid, 256>>>(value, logits, out);
    }
}

// round 2
// speedup vs baseline: 2.4371x; 2.4371x over previous
#include <cuda_runtime.h>
#include <math.h>

// Problem constants (fixed shapes)
#define N_BATCH 64
#define DIM     512   // d (contraction for QK)
#define CQ      512   // c (query positions)
#define TT      1024  // t = h*w
#define WW      128   // w
#define SCALE   0.04419417382415922f  // 512^-0.5

// 128 MB scratch for logits/weights [n][c][t]
static __device__ float g_logits[(size_t)N_BATCH * CQ * TT];

// ---------------------------------------------------------------------------
// helpers
// ---------------------------------------------------------------------------
__device__ __forceinline__ unsigned tf32r(float x) {
    unsigned u;
    asm("cvt.rna.tf32.f32 %0, %1;" : "=r"(u) : "f"(x));
    return u;
}

__device__ __forceinline__ void mma_tf32(float c[4],
                                         unsigned a0, unsigned a1, unsigned a2, unsigned a3,
                                         unsigned b0, unsigned b1) {
    asm volatile(
        "mma.sync.aligned.m16n8k8.row.col.f32.tf32.tf32.f32 "
        "{%0,%1,%2,%3}, {%4,%5,%6,%7}, {%8,%9}, {%0,%1,%2,%3};"
        : "+f"(c[0]), "+f"(c[1]), "+f"(c[2]), "+f"(c[3])
        : "r"(a0), "r"(a1), "r"(a2), "r"(a3), "r"(b0), "r"(b1));
}

#define KC 16  // K chunk per smem stage (2 x k8 mma steps)

// ---------------------------------------------------------------------------
// GEMM1 (TN): L[n][c][t] = SCALE * sum_d Q[n][d][c] * K[n][d][t]
// Global rows are d (contraction); c / t contiguous -> smem layout [k][m].
// CTA tile 128(c) x 128(t), 8 warps as 2(m) x 4(n), warp tile 64x32.
// ---------------------------------------------------------------------------
__global__ __launch_bounds__(256, 2) void gemm_qk_tf32(
    const float* __restrict__ Q, const float* __restrict__ Kp,
    float* __restrict__ L)
{
    const int n  = blockIdx.z;
    const float* Qb = Q  + (size_t)n * DIM * CQ;
    const float* Kb = Kp + (size_t)n * DIM * TT;
    float*       Lb = L  + (size_t)n * CQ  * TT;
    const int c0 = blockIdx.y * 128;
    const int t0 = blockIdx.x * 128;

    __shared__ unsigned As[KC][132];  // [k][m], pad 4 -> <=2-way frag conflicts
    __shared__ unsigned Bs[KC][132];  // [k][n]

    const int tid  = threadIdx.x;
    const int wid  = tid >> 5;
    const int lane = tid & 31;
    const int g    = lane >> 2;   // group id 0..7
    const int tig  = lane & 3;    // thread-in-group 0..3

    const int mOff = (wid >> 2) * 64;  // 0 or 64
    const int nOff = (wid & 3) * 32;   // 0,32,64,96

    float acc[4][4][4];
    #pragma unroll
    for (int i = 0; i < 4; i++)
        #pragma unroll
        for (int j = 0; j < 4; j++)
            #pragma unroll
            for (int r = 0; r < 4; r++) acc[i][j][r] = 0.f;

    // per-chunk global load: A tile KC x 128, B tile KC x 128
    // 16*32 = 512 float4 per tile; 2 per thread per tile.
    const int lrow0 = tid >> 5;          // tid/32: 0..7
    const int lcol  = (tid & 31) << 2;   // 0..124

    float4 ar[2], br[2];
    // prefetch chunk 0
    {
        ar[0] = *(const float4*)(Qb + (size_t)(lrow0    ) * CQ + c0 + lcol);
        ar[1] = *(const float4*)(Qb + (size_t)(lrow0 + 8) * CQ + c0 + lcol);
        br[0] = *(const float4*)(Kb + (size_t)(lrow0    ) * TT + t0 + lcol);
        br[1] = *(const float4*)(Kb + (size_t)(lrow0 + 8) * TT + t0 + lcol);
    }

    for (int k0 = 0; k0 < DIM; k0 += KC) {
        __syncthreads();
        #pragma unroll
        for (int u = 0; u < 2; u++) {
            int kr = lrow0 + 8 * u;
            As[kr][lcol + 0] = tf32r(u ? ar[1].x : ar[0].x);
            As[kr][lcol + 1] = tf32r(u ? ar[1].y : ar[0].y);
            As[kr][lcol + 2] = tf32r(u ? ar[1].z : ar[0].z);
            As[kr][lcol + 3] = tf32r(u ? ar[1].w : ar[0].w);
            Bs[kr][lcol + 0] = tf32r(u ? br[1].x : br[0].x);
            Bs[kr][lcol + 1] = tf32r(u ? br[1].y : br[0].y);
            Bs[kr][lcol + 2] = tf32r(u ? br[1].z : br[0].z);
            Bs[kr][lcol + 3] = tf32r(u ? br[1].w : br[0].w);
        }
        __syncthreads();

        if (k0 + KC < DIM) {
            const float* Qn = Qb + (size_t)(k0 + KC) * CQ;
            const float* Kn = Kb + (size_t)(k0 + KC) * TT;
            ar[0] = *(const float4*)(Qn + (size_t)(lrow0    ) * CQ + c0 + lcol);
            ar[1] = *(const float4*)(Qn + (size_t)(lrow0 + 8) * CQ + c0 + lcol);
            br[0] = *(const float4*)(Kn + (size_t)(lrow0    ) * TT + t0 + lcol);
            br[1] = *(const float4*)(Kn + (size_t)(lrow0 + 8) * TT + t0 + lcol);
        }

        #pragma unroll
        for (int s = 0; s < KC / 8; s++) {
            const int kk = s * 8;
            unsigned a[4][4];
            #pragma unroll
            for (int i = 0; i < 4; i++) {
                const int mb = mOff + 16 * i;
                a[i][0] = As[kk + tig    ][mb + g    ];
                a[i][1] = As[kk + tig    ][mb + g + 8];
                a[i][2] = As[kk + tig + 4][mb + g    ];
                a[i][3] = As[kk + tig + 4][mb + g + 8];
            }
            unsigned b[4][2];
            #pragma unroll
            for (int j = 0; j < 4; j++) {
                const int nb = nOff + 8 * j + g;
                b[j][0] = Bs[kk + tig    ][nb];
                b[j][1] = Bs[kk + tig + 4][nb];
            }
            #pragma unroll
            for (int i = 0; i < 4; i++)
                #pragma unroll
                for (int j = 0; j < 4; j++)
                    mma_tf32(acc[i][j], a[i][0], a[i][1], a[i][2], a[i][3],
                             b[j][0], b[j][1]);
        }
    }

    // epilogue: scale + store
    #pragma unroll
    for (int i = 0; i < 4; i++) {
        const int row0 = c0 + mOff + 16 * i + g;
        #pragma unroll
        for (int j = 0; j < 4; j++) {
            const int colb = t0 + nOff + 8 * j + 2 * tig;
            float2 lo = make_float2(acc[i][j][0] * SCALE, acc[i][j][1] * SCALE);
            float2 hi = make_float2(acc[i][j][2] * SCALE, acc[i][j][3] * SCALE);
            *(float2*)(Lb + (size_t)row0 * TT + colb)       = lo;
            *(float2*)(Lb + (size_t)(row0 + 8) * TT + colb) = hi;
        }
    }
}

// ---------------------------------------------------------------------------
// Fused mask + softmax over t. Mask: (t % 128) < vw[n],
// vw = min(128, floor(128*ratio + 0.5)).
// ---------------------------------------------------------------------------
__global__ __launch_bounds__(256) void softmax_mask_kernel(
    float* __restrict__ L, const float* __restrict__ ratios)
{
    const int row = blockIdx.x;
    const int n   = row >> 9;
    float* p = L + (size_t)row * TT;

    const float ratio = ratios[n];
    int vw = (int)floorf((float)WW * ratio + 0.5f);
    vw = vw > WW ? WW : vw;

    const int tid  = threadIdx.x;
    const int base = tid << 2;
    float4 v = ((const float4*)p)[tid];
    float vals[4] = {v.x, v.y, v.z, v.w};
    #pragma unroll
    for (int i = 0; i < 4; i++) {
        int wi = (base + i) & (WW - 1);
        if (wi >= vw) vals[i] = -INFINITY;
    }

    __shared__ float red_max[8];
    __shared__ float red_sum[8];
    const int lane = tid & 31;
    const int warp = tid >> 5;

    float m = fmaxf(fmaxf(vals[0], vals[1]), fmaxf(vals[2], vals[3]));
    #pragma unroll
    for (int off = 16; off > 0; off >>= 1)
        m = fmaxf(m, __shfl_xor_sync(0xffffffffu, m, off));
    if (lane == 0) red_max[warp] = m;
    __syncthreads();
    float mall = red_max[0];
    #pragma unroll
    for (int i = 1; i < 8; i++) mall = fmaxf(mall, red_max[i]);

    float s = 0.f;
    #pragma unroll
    for (int i = 0; i < 4; i++) {
        vals[i] = expf(vals[i] - mall);
        s += vals[i];
    }
    #pragma unroll
    for (int off = 16; off > 0; off >>= 1)
        s += __shfl_xor_sync(0xffffffffu, s, off);
    if (lane == 0) red_sum[warp] = s;
    __syncthreads();
    float sall = 0.f;
    #pragma unroll
    for (int i = 0; i < 8; i++) sall += red_sum[i];

    const float inv = 1.0f / sall;
    ((float4*)p)[tid] = make_float4(vals[0] * inv, vals[1] * inv,
                                    vals[2] * inv, vals[3] * inv);
}

// ---------------------------------------------------------------------------
// GEMM2 (NT): O[n][d][c] = sum_t V[n][d][t] * W[n][c][t]
// Contraction t contiguous for both -> smem layout [m][k] / [n][k],
// stride 20 -> conflict-free frag loads. CTA 128x128, warp 64x32.
// ---------------------------------------------------------------------------
__global__ __launch_bounds__(256, 2) void gemm_wv_tf32(
    const float* __restrict__ V, const float* __restrict__ W,
    float* __restrict__ O)
{
    const int n  = blockIdx.z;
    const float* Vb = V + (size_t)n * DIM * TT;
    const float* Wb = W + (size_t)n * CQ  * TT;
    float*       Ob = O + (size_t)n * DIM * CQ;
    const int d0 = blockIdx.y * 128;
    const int c0 = blockIdx.x * 128;

    __shared__ unsigned As[128][KC + 4];  // [m][k], stride 20 -> conflict-free
    __shared__ unsigned Bs[128][KC + 4];  // [n][k]

    const int tid  = threadIdx.x;
    const int wid  = tid >> 5;
    const int lane = tid & 31;
    const int g    = lane >> 2;
    const int tig  = lane & 3;

    const int mOff = (wid >> 2) * 64;
    const int nOff = (wid & 3) * 32;

    float acc[4][4][4];
    #pragma unroll
    for (int i = 0; i < 4; i++)
        #pragma unroll
        for (int j = 0; j < 4; j++)
            #pragma unroll
            for (int r = 0; r < 4; r++) acc[i][j][r] = 0.f;

    // per-chunk load: tile 128 rows x KC(16) cols = 512 float4; 2/thread.
    const int lrow = tid >> 1;          // 0..127
    const int lk   = (tid & 1) << 3;    // 0 or 8 (float4 pair base)

    float4 ar[2], br[2];
    {
        ar[0] = *(const float4*)(Vb + (size_t)(d0 + lrow) * TT + lk);
        ar[1] = *(const float4*)(Vb + (size_t)(d0 + lrow) * TT + lk + 4);
        br[0] = *(const float4*)(Wb + (size_t)(c0 + lrow) * TT + lk);
        br[1] = *(const float4*)(Wb + (size_t)(c0 + lrow) * TT + lk + 4);
    }

    for (int k0 = 0; k0 < TT; k0 += KC) {
        __syncthreads();
        As[lrow][lk + 0] = tf32r(ar[0].x);
        As[lrow][lk + 1] = tf32r(ar[0].y);
        As[lrow][lk + 2] = tf32r(ar[0].z);
        As[lrow][lk + 3] = tf32r(ar[0].w);
        As[lrow][lk + 4] = tf32r(ar[1].x);
        As[lrow][lk + 5] = tf32r(ar[1].y);
        As[lrow][lk + 6] = tf32r(ar[1].z);
        As[lrow][lk + 7] = tf32r(ar[1].w);
        Bs[lrow][lk + 0] = tf32r(br[0].x);
        Bs[lrow][lk + 1] = tf32r(br[0].y);
        Bs[lrow][lk + 2] = tf32r(br[0].z);
        Bs[lrow][lk + 3] = tf32r(br[0].w);
        Bs[lrow][lk + 4] = tf32r(br[1].x);
        Bs[lrow][lk + 5] = tf32r(br[1].y);
        Bs[lrow][lk + 6] = tf32r(br[1].z);
        Bs[lrow][lk + 7] = tf32r(br[1].w);
        __syncthreads();

        if (k0 + KC < TT) {
            const int kn = k0 + KC;
            ar[0] = *(const float4*)(Vb + (size_t)(d0 + lrow) * TT + kn + lk);
            ar[1] = *(const float4*)(Vb + (size_t)(d0 + lrow) * TT + kn + lk + 4);
            br[0] = *(const float4*)(Wb + (size_t)(c0 + lrow) * TT + kn + lk);
            br[1] = *(const float4*)(Wb + (size_t)(c0 + lrow) * TT + kn + lk + 4);
        }

        #pragma unroll
        for (int s = 0; s < KC / 8; s++) {
            const int kk = s * 8;
            unsigned a[4][4];
            #pragma unroll
            for (int i = 0; i < 4; i++) {
                const int mb = mOff + 16 * i;
                a[i][0] = As[mb + g    ][kk + tig    ];
                a[i][1] = As[mb + g + 8][kk + tig    ];
                a[i][2] = As[mb + g    ][kk + tig + 4];
                a[i][3] = As[mb + g + 8][kk + tig + 4];
            }
            unsigned b[4][2];
            #pragma unroll
            for (int j = 0; j < 4; j++) {
                const int nb = nOff + 8 * j + g;
                b[j][0] = Bs[nb][kk + tig    ];
                b[j][1] = Bs[nb][kk + tig + 4];
            }
            #pragma unroll
            for (int i = 0; i < 4; i++)
                #pragma unroll
                for (int j = 0; j < 4; j++)
                    mma_tf32(acc[i][j], a[i][0], a[i][1], a[i][2], a[i][3],
                             b[j][0], b[j][1]);
        }
    }

    #pragma unroll
    for (int i = 0; i < 4; i++) {
        const int row0 = d0 + mOff + 16 * i + g;
        #pragma unroll
        for (int j = 0; j < 4; j++) {
            const int colb = c0 + nOff + 8 * j + 2 * tig;
            *(float2*)(Ob + (size_t)row0 * CQ + colb) =
                make_float2(acc[i][j][0], acc[i][j][1]);
            *(float2*)(Ob + (size_t)(row0 + 8) * CQ + colb) =
                make_float2(acc[i][j][2], acc[i][j][3]);
        }
    }
}

// ---------------------------------------------------------------------------
extern "C" void kernel_launch(void* const* d_in, const int* in_sizes, int n_in,
                              void* d_out, int out_size)
{
    const float* query  = (const float*)d_in[0];  // [64, 512, 512]
    const float* key    = (const float*)d_in[1];  // [64, 512, 1024]
    const float* value  = (const float*)d_in[2];  // [64, 512, 1024]
    const float* ratios = (const float*)d_in[3];  // [64]
    float* out = (float*)d_out;                   // [64, 512, 512]

    float* logits = nullptr;
    cudaGetSymbolAddress((void**)&logits, g_logits);

    {
        dim3 grid(TT / 128, CQ / 128, N_BATCH);  // (8, 4, 64)
        gemm_qk_tf32<<<grid, 256>>>(query, key, logits);
    }
    {
        softmax_mask_kernel<<<N_BATCH * CQ, 256>>>(logits, ratios);
    }
    {
        dim3 grid(CQ / 128, DIM / 128, N_BATCH);  // (4, 4, 64)
        gemm_wv_tf32<<<grid, 256>>>(value, logits, out);
    }
}